// round 16
// baseline (speedup 1.0000x reference)
#include <cuda_runtime.h>
#include <cuda_bf16.h>
#include <cstdint>

// Problem dims (fixed by the dataset)
#define BB 8
#define NSEQ 2048
#define DD 1024
#define DKK 64
#define MTOT (BB*NSEQ)   // 16384

// ---------------- scratch (static __device__ — no allocation) ----------------
__device__ float    g_QKFP[(long)MTOT*256];  // Q[0:64] _ F[128:192] _ (K,P stay local)
__device__ float    g_U2part[32*DKK*DD];     // split-K partials of U2
__device__ float    g_Tpart[256*DKK*DKK];    // per-qkfp-block T partials
__device__ float    g_T[BB*DKK*DKK];         // reduced T
__device__ uint32_t g_Wh[256*512];           // Wext bf16-hi, packed k-pairs
__device__ uint32_t g_Wl[64*512];            // Wext bf16-lo, rows 128..191 (W1)
__device__ uint32_t g_W2h[1024*32];          // W2 bf16-hi packed
__device__ uint32_t g_W2l[1024*32];          // W2 bf16-lo packed

// ---------------------------------------------------------------------------
// helpers
// ---------------------------------------------------------------------------
__device__ __forceinline__ uint32_t b2u(__nv_bfloat162 v) {
    return *reinterpret_cast<uint32_t*>(&v);
}
__device__ __forceinline__ void cvt_hilo(float x, float y,
                                         __nv_bfloat162& h, __nv_bfloat162& l)
{
    h = __floats2bfloat162_rn(x, y);
    l = __floats2bfloat162_rn(x - __bfloat162float(h.x), y - __bfloat162float(h.y));
}

__device__ __forceinline__ void mma_bf16(float (&d)[4],
    const uint32_t (&a)[4], const uint32_t (&b)[2])
{
    asm volatile(
        "mma.sync.aligned.m16n8k16.row.col.f32.bf16.bf16.f32 "
        "{%0,%1,%2,%3},{%4,%5,%6,%7},{%8,%9},{%0,%1,%2,%3};"
        : "+f"(d[0]), "+f"(d[1]), "+f"(d[2]), "+f"(d[3])
        : "r"(a[0]), "r"(a[1]), "r"(a[2]), "r"(a[3]), "r"(b[0]), "r"(b[1]));
}

__device__ __forceinline__ void ldmx4(uint32_t (&r)[4], uint32_t addr) {
    asm volatile("ldmatrix.sync.aligned.m8n8.x4.shared.b16 {%0,%1,%2,%3}, [%4];"
        : "=r"(r[0]), "=r"(r[1]), "=r"(r[2]), "=r"(r[3]) : "r"(addr));
}
__device__ __forceinline__ void ldmx2(uint32_t (&r)[2], uint32_t addr) {
    asm volatile("ldmatrix.sync.aligned.m8n8.x2.shared.b16 {%0,%1}, [%2];"
        : "=r"(r[0]), "=r"(r[1]) : "r"(addr));
}

__device__ __forceinline__ void cp16(uint32_t smem_addr, const void* gptr) {
    asm volatile("cp.async.cg.shared.global [%0], [%1], 16;"
        :: "r"(smem_addr), "l"(gptr));
}
__device__ __forceinline__ void cp_commit() {
    asm volatile("cp.async.commit_group;" ::: "memory");
}
__device__ __forceinline__ void cp_wait0() {
    asm volatile("cp.async.wait_group 0;" ::: "memory");
}
__device__ __forceinline__ void cp_wait1() {
    asm volatile("cp.async.wait_group 1;" ::: "memory");
}

// ===========================================================================
// prep_w: builds bf16 weight planes directly from the inputs.
// Wh rows: 0..63 Wq, 64..127 Wk, 128..191 W1 (lo plane -> Wl), 192..255 U2
// (U2 summed inline from the 32 split-K partials). Also W2 -> W2h/W2l.
// ===========================================================================
__global__ void prep_w(const float* __restrict__ Wq, const float* __restrict__ Wk,
                       const float* __restrict__ W1, const float* __restrict__ u2p,
                       const float* __restrict__ W2,
                       uint32_t* __restrict__ Wh, uint32_t* __restrict__ Wl,
                       uint32_t* __restrict__ W2h, uint32_t* __restrict__ W2l)
{
    int i = blockIdx.x * 256 + threadIdx.x;
    if (i < 256*512) {
        int row = i >> 9, p = i & 511;
        float x, y;
        if (row < 128) {
            const float* W = (row < 64) ? Wq : Wk;
            int r = row & 63;
            x = W[r*DD + 2*p];  y = W[r*DD + 2*p + 1];
        } else if (row < 192) {
            int r = row - 128;
            x = W1[r*DD + 2*p];  y = W1[r*DD + 2*p + 1];
        } else {
            int r = row - 192;
            float sx = 0.f, sy = 0.f;
            for (int s = 0; s < 32; s++) {
                sx += u2p[(long)s*DKK*DD + r*DD + 2*p];
                sy += u2p[(long)s*DKK*DD + r*DD + 2*p + 1];
            }
            x = sx;  y = sy;
        }
        __nv_bfloat162 h, l;
        cvt_hilo(x, y, h, l);
        Wh[i] = b2u(h);
        if (row >= 128 && row < 192) Wl[(row - 128) * 512 + p] = b2u(l);
    } else {
        int j = i - 256*512;
        if (j < 1024*32) {
            __nv_bfloat162 h, l;
            cvt_hilo(W2[2*j], W2[2*j + 1], h, l);
            W2h[j] = b2u(h);
            W2l[j] = b2u(l);
        }
    }
}

// ===========================================================================
// qkfp_fused: C[M,256] = x[M,1024] * Wext[256,1024]^T, ONE pass over x.
// R13 mainloop (interleaved MMA ordering, 2 blocks/SM, 2-stage pipeline).
// Epilogue: writes only Q (cols 0..63) and F (128..191) to global; K and P
// accumulators go to smem (stage area is free after the mainloop), and the
// block computes its own 64-row T partial Tpart[bx] = K_chunk^T @ P_chunk
// in fp32 SIMT (replaces the separate tgemm_atb kernel entirely).
// ===========================================================================
extern __shared__ uint32_t smem_dyn[];

__global__ void __launch_bounds__(256, 2)
qkfp_fused(const float* __restrict__ xg, const uint32_t* __restrict__ Wh,
           const uint32_t* __restrict__ Wl, float* __restrict__ Cg,
           float* __restrict__ tpart)
{
    constexpr int SP = 20;
    constexpr int OA_L = 1280;
    constexpr int OB_H = 2560;
    constexpr int OB_L = 7680;
    constexpr int STG  = 8960;
    constexpr uint32_t STGB = STG * 4;

    uint32_t* Ahs = smem_dyn;

    const int m0 = blockIdx.x * 64;
    const int tid = threadIdx.x, lane = tid & 31, wid = tid >> 5;
    const int wn = wid;

    const uint32_t sbase = (uint32_t)__cvta_generic_to_shared(smem_dyn);

    const int arowoff = ((lane >> 3) & 1) * 8 + (lane & 7);
    const int akoff   = (lane >> 4) * 4;
    uint32_t a_addr[4];
    #pragma unroll
    for (int mt = 0; mt < 4; mt++)
        a_addr[mt] = sbase + ((mt * 16 + arowoff) * SP + akoff) * 4;
    const uint32_t dAl = OA_L * 4;
    const int lb = lane & 15;
    uint32_t b_addr[4], bl_addr;
    #pragma unroll
    for (int j = 0; j < 4; j++)
        b_addr[j] = sbase + (OB_H + (wn * 8 + j * 64 + (lb & 7)) * SP
                             + ((lb >> 3) & 1) * 4) * 4;
    bl_addr = sbase + (OB_L + (wn * 8 + (lb & 7)) * SP + ((lb >> 3) & 1) * 4) * 4;

    const int ar = tid >> 3, afq = (tid & 7) * 4;
    const int aso = ar * SP + (afq >> 1);
    const int br = tid >> 2, bc = (tid & 3) * 4;

    float4 va[2];
    auto ldgA = [&](int k0) {
        #pragma unroll
        for (int e = 0; e < 2; e++)
            va[e] = *(const float4*)(xg + (long)(m0 + ar + e*32) * DD + k0 + afq);
    };
    auto cpB = [&](int k0, int s) {
        uint32_t d0 = sbase + (s * STG + OB_H + br * SP + bc) * 4;
        #pragma unroll
        for (int e = 0; e < 4; e++)
            cp16(d0 + e * 64 * SP * 4, &Wh[(br + e*64) * 512 + (k0 >> 1) + bc]);
        cp16(sbase + (s * STG + OB_L + br * SP + bc) * 4,
             &Wl[br * 512 + (k0 >> 1) + bc]);
        cp_commit();
    };
    auto stA = [&](int s) {
        #pragma unroll
        for (int e = 0; e < 2; e++) {
            float4 v = va[e];
            __nv_bfloat162 h0, l0, h1, l1;
            cvt_hilo(v.x, v.y, h0, l0);  cvt_hilo(v.z, v.w, h1, l1);
            int o = s * STG + aso + e * 32 * SP;
            Ahs[o]        = b2u(h0);  Ahs[o + 1]        = b2u(h1);
            Ahs[OA_L + o] = b2u(l0);  Ahs[OA_L + o + 1] = b2u(l1);
        }
    };

    float acc[4][4][4] = {};

    ldgA(0);
    cpB(0, 0);
    stA(0);
    cp_wait0();
    __syncthreads();

    int s = 0;
    for (int k0 = 0; k0 < DD; k0 += 32, s ^= 1) {
        const bool more = (k0 + 32) < DD;
        if (more) {
            ldgA(k0 + 32);
            cpB(k0 + 32, s ^ 1);
        }

        const uint32_t so = s * STGB;
        #pragma unroll
        for (int kp = 0; kp < 2; kp++) {
            const uint32_t kb = so + kp * 32;
            uint32_t bh[4][2], bl2[2];
            #pragma unroll
            for (int j = 0; j < 4; j++) ldmx2(bh[j], b_addr[j] + kb);
            ldmx2(bl2, bl_addr + kb);
            #pragma unroll
            for (int mt = 0; mt < 4; mt++) {
                uint32_t ah4[4], al4[4];
                ldmx4(ah4, a_addr[mt] + kb);
                #pragma unroll
                for (int j = 0; j < 4; j++)
                    mma_bf16(acc[mt][j], ah4, bh[j]);
                ldmx4(al4, a_addr[mt] + dAl + kb);
                mma_bf16(acc[mt][2], ah4, bl2);    // hi*lo (F)
                mma_bf16(acc[mt][2], al4, bh[2]);  // lo*hi (F)
            }
        }

        if (more) stA(s ^ 1);
        cp_wait0();
        __syncthreads();
    }

    // ---- epilogue: Q,F -> global; K,P -> smem (stage area is now free) ----
    float* Ks = (float*)smem_dyn;             // [64][68] fp32 (17408 B)
    float* Ps = Ks + 64 * 68;                 // [64][68] fp32 (34816 B total)

    const int r4 = lane >> 2, c4 = lane & 3;
    #pragma unroll
    for (int mt = 0; mt < 4; mt++) {
        const int row = mt * 16 + r4;
        const int col = wn * 8 + 2 * c4;
        // Q (j=0) and F (j=2) to global
        *(float2*)(Cg + (long)(m0 + row) * 256 + col) =
            make_float2(acc[mt][0][0], acc[mt][0][1]);
        *(float2*)(Cg + (long)(m0 + row + 8) * 256 + col) =
            make_float2(acc[mt][0][2], acc[mt][0][3]);
        *(float2*)(Cg + (long)(m0 + row) * 256 + 128 + col) =
            make_float2(acc[mt][2][0], acc[mt][2][1]);
        *(float2*)(Cg + (long)(m0 + row + 8) * 256 + 128 + col) =
            make_float2(acc[mt][2][2], acc[mt][2][3]);
        // K (j=1) and P (j=3) to smem
        *(float2*)&Ks[row * 68 + col]       = make_float2(acc[mt][1][0], acc[mt][1][1]);
        *(float2*)&Ks[(row + 8) * 68 + col] = make_float2(acc[mt][1][2], acc[mt][1][3]);
        *(float2*)&Ps[row * 68 + col]       = make_float2(acc[mt][3][0], acc[mt][3][1]);
        *(float2*)&Ps[(row + 8) * 68 + col] = make_float2(acc[mt][3][2], acc[mt][3][3]);
    }
    __syncthreads();

    // T partial: T[i][j] = sum_r Ks[r][i] * Ps[r][j], fp32 SIMT
    {
        const int ti  = tid >> 2;
        const int tj0 = (tid & 3) * 16;
        float tacc[16] = {};
        #pragma unroll 8
        for (int r = 0; r < 64; r++) {
            float kv = Ks[r * 68 + ti];
            #pragma unroll
            for (int jj = 0; jj < 16; jj += 4) {
                float4 pv = *(const float4*)&Ps[r * 68 + tj0 + jj];
                tacc[jj]   += kv * pv.x;  tacc[jj+1] += kv * pv.y;
                tacc[jj+2] += kv * pv.z;  tacc[jj+3] += kv * pv.w;
            }
        }
        float* dst = tpart + (long)blockIdx.x * 4096 + ti * 64 + tj0;
        #pragma unroll
        for (int jj = 0; jj < 16; jj += 4) {
            float4 v;
            v.x = tacc[jj];   v.y = tacc[jj+1];
            v.z = tacc[jj+2]; v.w = tacc[jj+3];
            *(float4*)(dst + jj) = v;
        }
    }
}

// ===========================================================================
// reduceT: T[b] = sum of the 32 contiguous qkfp-block partials of batch b.
// ===========================================================================
__global__ void reduceT(const float* __restrict__ p, float* __restrict__ o)
{
    int i = blockIdx.x * 256 + threadIdx.x;      // 32768 total
    int b = i >> 12, e = i & 4095;
    const float* src = p + (long)b * 32 * 4096 + e;
    float s = 0.f;
    #pragma unroll 8
    for (int k = 0; k < 32; k++) s += src[(long)k * 4096];
    o[i] = s;
}

// ===========================================================================
// fcout: fused fc + out (R13 winner, unchanged).
// ===========================================================================
__global__ void __launch_bounds__(256, 2)
fcout(const float* __restrict__ qkfp, const float* __restrict__ T,
      const uint32_t* __restrict__ W2h, const uint32_t* __restrict__ W2l,
      float* __restrict__ out)
{
    constexpr int SP = 36;
    constexpr int O_TS = 4352;
    constexpr int O_AH = 8704;
    constexpr int O_AL = 11008;
    constexpr int O_B  = 13312;
    constexpr int BSTG = 4608;
    constexpr int O_BL = 2304;

    float*    Qs  = (float*)smem_dyn;
    float*    Ts  = (float*)smem_dyn + O_TS;
    uint32_t* Ahp = smem_dyn + O_AH;
    uint32_t* Alp = smem_dyn + O_AL;

    const int r0 = blockIdx.x * 64;
    const int b  = r0 / NSEQ;
    const int tid = threadIdx.x, lane = tid & 31, wid = tid >> 5;
    const uint32_t sbase = (uint32_t)__cvta_generic_to_shared(smem_dyn);

    #pragma unroll
    for (int e = 0; e < 4; e++) {
        int idx = tid + e * 256;
        int row = idx >> 4, fq = idx & 15;
        float4 q = *(const float4*)(qkfp + (long)(r0 + row) * 256 + fq * 4);
        *(float4*)&Qs[row * 68 + fq * 4] = q;
        float4 t = *(const float4*)(T + (long)b * 4096 + row * 64 + fq * 4);
        *(float4*)&Ts[row * 68 + fq * 4] = t;
    }
    __syncthreads();

    {
        const int row  = tid >> 2;
        const int col0 = (tid & 3) * 16;
        float acc[16];
        #pragma unroll
        for (int j = 0; j < 16; j += 4) {
            float4 f = *(const float4*)(qkfp + (long)(r0 + row) * 256 + 128 + col0 + j);
            acc[j] = f.x; acc[j+1] = f.y; acc[j+2] = f.z; acc[j+3] = f.w;
        }
        #pragma unroll 8
        for (int k = 0; k < 64; k++) {
            float q = Qs[row * 68 + k];
            #pragma unroll
            for (int j = 0; j < 16; j += 4) {
                float4 t = *(const float4*)&Ts[k * 68 + col0 + j];
                acc[j]   += q * t.x;  acc[j+1] += q * t.y;
                acc[j+2] += q * t.z;  acc[j+3] += q * t.w;
            }
        }
        const int ob = row * SP + (col0 >> 1);
        #pragma unroll
        for (int jj = 0; jj < 8; jj++) {
            __nv_bfloat162 h, l;
            cvt_hilo(acc[2*jj], acc[2*jj + 1], h, l);
            Ahp[ob + jj] = b2u(h);
            Alp[ob + jj] = b2u(l);
        }
    }

    const int wm0 = (wid & 1) * 32, wn0 = (wid >> 1) * 16;
    const int arowoff = ((lane >> 3) & 1) * 8 + (lane & 7);
    const int akoff   = (lane >> 4) * 4;
    uint32_t a_addr[2];
    #pragma unroll
    for (int mt = 0; mt < 2; mt++)
        a_addr[mt] = sbase + (O_AH + (wm0 + mt * 16 + arowoff) * SP + akoff) * 4;
    const uint32_t dAl = (O_AL - O_AH) * 4;
    const int lb = lane & 15;
    uint32_t b_addr[2];
    #pragma unroll
    for (int nt = 0; nt < 2; nt++)
        b_addr[nt] = sbase + (O_B + (wn0 + nt * 8 + (lb & 7)) * SP
                              + ((lb >> 3) & 1) * 4) * 4;
    const uint32_t dBl = O_BL * 4;

    const int wr = tid >> 3, wc = (tid & 7) * 4;
    auto cpW = [&](int nt, int s) {
        uint32_t d0 = sbase + (O_B + s * BSTG + wr * SP + wc) * 4;
        cp16(d0,            &W2h[(long)(nt * 64 + wr) * 32 + wc]);
        cp16(d0 + dBl,      &W2l[(long)(nt * 64 + wr) * 32 + wc]);
        uint32_t d1 = sbase + (O_B + s * BSTG + (wr + 32) * SP + wc) * 4;
        cp16(d1,            &W2h[(long)(nt * 64 + wr + 32) * 32 + wc]);
        cp16(d1 + dBl,      &W2l[(long)(nt * 64 + wr + 32) * 32 + wc]);
        cp_commit();
    };

    cpW(0, 0);

    const int r4 = lane >> 2, c4 = lane & 3;
    int s = 0;
    for (int nt = 0; nt < 16; nt++, s ^= 1) {
        if (nt < 15) {
            cpW(nt + 1, s ^ 1);
            cp_wait1();
        } else {
            cp_wait0();
        }
        __syncthreads();

        const uint32_t sB = s * BSTG * 4;
        float acc[2][2][4] = {};
        #pragma unroll
        for (int kp = 0; kp < 4; kp++) {
            const uint32_t kb = kp * 32;
            uint32_t ah[2][4], al[2][4], bh[2][2], bl[2][2];
            #pragma unroll
            for (int mt = 0; mt < 2; mt++) ldmx4(ah[mt], a_addr[mt] + kb);
            #pragma unroll
            for (int ns = 0; ns < 2; ns++) ldmx2(bh[ns], b_addr[ns] + sB + kb);
            #pragma unroll
            for (int mt = 0; mt < 2; mt++) ldmx4(al[mt], a_addr[mt] + dAl + kb);
            #pragma unroll
            for (int ns = 0; ns < 2; ns++) ldmx2(bl[ns], b_addr[ns] + sB + dBl + kb);
            #pragma unroll
            for (int mt = 0; mt < 2; mt++)
                #pragma unroll
                for (int ns = 0; ns < 2; ns++) {
                    mma_bf16(acc[mt][ns], ah[mt], bh[ns]);
                    mma_bf16(acc[mt][ns], ah[mt], bl[ns]);
                    mma_bf16(acc[mt][ns], al[mt], bh[ns]);
                }
        }

        #pragma unroll
        for (int mt = 0; mt < 2; mt++)
            #pragma unroll
            for (int ns = 0; ns < 2; ns++) {
                int row = r0 + wm0 + mt * 16 + r4;
                int col = nt * 64 + wn0 + ns * 8 + 2 * c4;
                *(float2*)(out + (long)row * 1024 + col) =
                    make_float2(acc[mt][ns][0], acc[mt][ns][1]);
                *(float2*)(out + (long)(row + 8) * 1024 + col) =
                    make_float2(acc[mt][ns][2], acc[mt][ns][3]);
            }
        __syncthreads();
    }
}

// ===========================================================================
// SIMT fp32 NN GEMM (U2 only): C[M,N] = A[M,K]*B[K,N], split-K via z
// ===========================================================================
template<int BM,int BN,int BK,int TM,int TN>
__global__ void __launch_bounds__((BM/TM)*(BN/TN))
gemm_nn(const float* __restrict__ A, long sA, int lda,
        const float* __restrict__ B, long sB, int ldb,
        float* __restrict__ C, long sC, int ldc,
        int K)
{
    constexpr int THREADS = (BM/TM)*(BN/TN);
    __shared__ float As[BK][BM];
    __shared__ float Bs[BK][BN];

    const int bz = blockIdx.z;
    A += bz * sA;  B += bz * sB;  C += bz * sC;

    const int m0 = blockIdx.y * BM;
    const int n0 = blockIdx.x * BN;
    const int tid = threadIdx.x;
    const int tx = tid % (BN/TN);
    const int ty = tid / (BN/TN);

    float acc[TM][TN];
    #pragma unroll
    for (int i = 0; i < TM; i++)
        #pragma unroll
        for (int j = 0; j < TN; j++) acc[i][j] = 0.f;

    for (int k0 = 0; k0 < K; k0 += BK) {
        #pragma unroll
        for (int e = 0; e < (BM*BK/4)/THREADS; e++) {
            int idx = tid + e*THREADS;
            int row = idx / (BK/4), cv = idx % (BK/4);
            float4 v = *(const float4*)(A + (long)(m0+row)*lda + k0 + cv*4);
            As[cv*4+0][row] = v.x;  As[cv*4+1][row] = v.y;
            As[cv*4+2][row] = v.z;  As[cv*4+3][row] = v.w;
        }
        #pragma unroll
        for (int e = 0; e < (BK*BN/4)/THREADS; e++) {
            int idx = tid + e*THREADS;
            int row = idx / (BN/4), cv = idx % (BN/4);
            *(float4*)&Bs[row][cv*4] =
                *(const float4*)(B + (long)(k0+row)*ldb + n0 + cv*4);
        }
        __syncthreads();
        #pragma unroll
        for (int k = 0; k < BK; k++) {
            float a[TM], b[TN];
            #pragma unroll
            for (int i = 0; i < TM; i += 4) *(float4*)(a+i) = *(const float4*)&As[k][ty*TM+i];
            #pragma unroll
            for (int j = 0; j < TN; j += 4) *(float4*)(b+j) = *(const float4*)&Bs[k][tx*TN+j];
            #pragma unroll
            for (int i = 0; i < TM; i++)
                #pragma unroll
                for (int j = 0; j < TN; j++) acc[i][j] += a[i]*b[j];
        }
        __syncthreads();
    }
    #pragma unroll
    for (int i = 0; i < TM; i++) {
        int row = m0 + ty*TM + i;
        #pragma unroll
        for (int j = 0; j < TN; j += 4) {
            float4 v;
            v.x = acc[i][j];   v.y = acc[i][j+1];
            v.z = acc[i][j+2]; v.w = acc[i][j+3];
            *(float4*)(C + (long)row*ldc + n0 + tx*TN + j) = v;
        }
    }
}

// ============================================================================
extern "C" void kernel_launch(void* const* d_in, const int* in_sizes, int n_in,
                              void* d_out, int out_size)
{
    const float* x  = (const float*)d_in[0];   // [8,2048,1024]
    const float* Wq = (const float*)d_in[1];   // [64,1024]
    const float* Wk = (const float*)d_in[2];   // [64,1024]
    const float* Wv = (const float*)d_in[3];   // [1024,1024]
    const float* W1 = (const float*)d_in[4];   // [64,1024]
    const float* W2 = (const float*)d_in[5];   // [1024,64]
    float* out = (float*)d_out;                // [8,2048,1024]

    float *qkfp, *u2p, *tpart, *gt;
    uint32_t *wh, *wl, *w2h, *w2l;
    cudaGetSymbolAddress((void**)&qkfp,  g_QKFP);
    cudaGetSymbolAddress((void**)&u2p,   g_U2part);
    cudaGetSymbolAddress((void**)&tpart, g_Tpart);
    cudaGetSymbolAddress((void**)&gt,    g_T);
    cudaGetSymbolAddress((void**)&wh,    g_Wh);
    cudaGetSymbolAddress((void**)&wl,    g_Wl);
    cudaGetSymbolAddress((void**)&w2h,   g_W2h);
    cudaGetSymbolAddress((void**)&w2l,   g_W2l);

    static_assert(2 * 8960 * 4 == 71680, "qkfp stage size");
    cudaFuncSetAttribute(qkfp_fused,
                         cudaFuncAttributeMaxDynamicSharedMemorySize, 71680);
    static_assert(22528 * 4 == 90112, "fcout smem size");
    cudaFuncSetAttribute(fcout,
                         cudaFuncAttributeMaxDynamicSharedMemorySize, 90112);

    // U2 = W1 @ Wv : [64,1024], 32-way split-K partials (R13 config)
    gemm_nn<64,64,16,4,4><<<dim3(16,1,32), 256>>>(
        W1, 32, DD,  Wv, (long)32*DD, DD,  u2p, (long)DKK*DD, DD,  32);

    // Build all bf16 weight planes
    prep_w<<<(256*512 + 1024*32 + 255)/256, 256>>>(
        Wq, Wk, W1, u2p, W2, wh, wl, w2h, w2l);

    // QKFP (Q,F to global) + per-block T partials, one pass over x
    qkfp_fused<<<256, 256, 71680>>>(x, wh, wl, qkfp, tpart);

    // T[b] = sum of batch b's 32 block partials
    reduceT<<<(BB*DKK*DKK + 255)/256, 256>>>(tpart, gt);

    // fused fc + out
    fcout<<<256, 256, 90112>>>(qkfp, gt, w2h, w2l, out);
}

// round 17
// speedup vs baseline: 1.1411x; 1.1411x over previous
#include <cuda_runtime.h>
#include <cuda_bf16.h>
#include <cstdint>

// Problem dims (fixed by the dataset)
#define BB 8
#define NSEQ 2048
#define DD 1024
#define DKK 64
#define MTOT (BB*NSEQ)   // 16384

// ---------------- scratch (static __device__ — no allocation) ----------------
__device__ float    g_QKFP[(long)MTOT*256];  // Q[0:64] K[64:128] F[128:192] P[192:256]
__device__ float    g_U2part[32*DKK*DD];     // split-K partials of U2
__device__ float    g_Tpart[32*BB*DKK*DKK];  // split-L partials of T
__device__ float    g_T[BB*DKK*DKK];         // reduced T
__device__ uint32_t g_Wh[256*512];           // Wext bf16-hi, packed k-pairs
__device__ uint32_t g_Wl[64*512];            // Wext bf16-lo, rows 128..191 (W1)
__device__ uint32_t g_W2h[1024*32];          // W2 bf16-hi packed
__device__ uint32_t g_W2l[1024*32];          // W2 bf16-lo packed

// ---------------------------------------------------------------------------
// helpers
// ---------------------------------------------------------------------------
__device__ __forceinline__ float tf32_rna(float x) {
    uint32_t r;
    asm("cvt.rna.tf32.f32 %0, %1;" : "=r"(r) : "f"(x));
    return __uint_as_float(r);
}
__device__ __forceinline__ uint32_t f2u(float f) { return __float_as_uint(f); }
__device__ __forceinline__ uint32_t b2u(__nv_bfloat162 v) {
    return *reinterpret_cast<uint32_t*>(&v);
}
__device__ __forceinline__ void cvt_hilo(float x, float y,
                                         __nv_bfloat162& h, __nv_bfloat162& l)
{
    h = __floats2bfloat162_rn(x, y);
    l = __floats2bfloat162_rn(x - __bfloat162float(h.x), y - __bfloat162float(h.y));
}

__device__ __forceinline__ void mma_tf32(float (&d)[4],
    uint32_t a0, uint32_t a1, uint32_t a2, uint32_t a3,
    uint32_t b0, uint32_t b1)
{
    asm volatile(
        "mma.sync.aligned.m16n8k8.row.col.f32.tf32.tf32.f32 "
        "{%0,%1,%2,%3},{%4,%5,%6,%7},{%8,%9},{%0,%1,%2,%3};"
        : "+f"(d[0]), "+f"(d[1]), "+f"(d[2]), "+f"(d[3])
        : "r"(a0), "r"(a1), "r"(a2), "r"(a3), "r"(b0), "r"(b1));
}

__device__ __forceinline__ void mma_bf16(float (&d)[4],
    const uint32_t (&a)[4], const uint32_t (&b)[2])
{
    asm volatile(
        "mma.sync.aligned.m16n8k16.row.col.f32.bf16.bf16.f32 "
        "{%0,%1,%2,%3},{%4,%5,%6,%7},{%8,%9},{%0,%1,%2,%3};"
        : "+f"(d[0]), "+f"(d[1]), "+f"(d[2]), "+f"(d[3])
        : "r"(a[0]), "r"(a[1]), "r"(a[2]), "r"(a[3]), "r"(b[0]), "r"(b[1]));
}

__device__ __forceinline__ void ldmx4(uint32_t (&r)[4], uint32_t addr) {
    asm volatile("ldmatrix.sync.aligned.m8n8.x4.shared.b16 {%0,%1,%2,%3}, [%4];"
        : "=r"(r[0]), "=r"(r[1]), "=r"(r[2]), "=r"(r[3]) : "r"(addr));
}
__device__ __forceinline__ void ldmx2(uint32_t (&r)[2], uint32_t addr) {
    asm volatile("ldmatrix.sync.aligned.m8n8.x2.shared.b16 {%0,%1}, [%2];"
        : "=r"(r[0]), "=r"(r[1]) : "r"(addr));
}

__device__ __forceinline__ void cp16(uint32_t smem_addr, const void* gptr) {
    asm volatile("cp.async.cg.shared.global [%0], [%1], 16;"
        :: "r"(smem_addr), "l"(gptr));
}
__device__ __forceinline__ void cp_commit() {
    asm volatile("cp.async.commit_group;" ::: "memory");
}
__device__ __forceinline__ void cp_wait0() {
    asm volatile("cp.async.wait_group 0;" ::: "memory");
}
__device__ __forceinline__ void cp_wait1() {
    asm volatile("cp.async.wait_group 1;" ::: "memory");
}

// ===========================================================================
// prep_w: builds bf16 weight planes directly from the inputs.
// Wh rows: 0..63 Wq, 64..127 Wk, 128..191 W1 (lo plane -> Wl), 192..255 U2
// (U2 summed inline from the 32 split-K partials). Also W2 -> W2h/W2l.
// ===========================================================================
__global__ void prep_w(const float* __restrict__ Wq, const float* __restrict__ Wk,
                       const float* __restrict__ W1, const float* __restrict__ u2p,
                       const float* __restrict__ W2,
                       uint32_t* __restrict__ Wh, uint32_t* __restrict__ Wl,
                       uint32_t* __restrict__ W2h, uint32_t* __restrict__ W2l)
{
    int i = blockIdx.x * 256 + threadIdx.x;
    if (i < 256*512) {
        int row = i >> 9, p = i & 511;
        float x, y;
        if (row < 128) {
            const float* W = (row < 64) ? Wq : Wk;
            int r = row & 63;
            x = W[r*DD + 2*p];  y = W[r*DD + 2*p + 1];
        } else if (row < 192) {
            int r = row - 128;
            x = W1[r*DD + 2*p];  y = W1[r*DD + 2*p + 1];
        } else {
            int r = row - 192;
            float sx = 0.f, sy = 0.f;
            for (int s = 0; s < 32; s++) {
                sx += u2p[(long)s*DKK*DD + r*DD + 2*p];
                sy += u2p[(long)s*DKK*DD + r*DD + 2*p + 1];
            }
            x = sx;  y = sy;
        }
        __nv_bfloat162 h, l;
        cvt_hilo(x, y, h, l);
        Wh[i] = b2u(h);
        if (row >= 128 && row < 192) Wl[(row - 128) * 512 + p] = b2u(l);
    } else {
        int j = i - 256*512;
        if (j < 1024*32) {
            __nv_bfloat162 h, l;
            cvt_hilo(W2[2*j], W2[2*j + 1], h, l);
            W2h[j] = b2u(h);
            W2l[j] = b2u(l);
        }
    }
}

// ===========================================================================
// qkfp_fused: C[M,256] = x[M,1024] * Wext[256,1024]^T, ONE pass over x.
// (R13 configuration — interleaved MMA ordering, 2 blocks/SM.)
// ===========================================================================
extern __shared__ uint32_t smem_dyn[];

__global__ void __launch_bounds__(256, 2)
qkfp_fused(const float* __restrict__ xg, const uint32_t* __restrict__ Wh,
           const uint32_t* __restrict__ Wl, float* __restrict__ Cg)
{
    constexpr int SP = 20;
    constexpr int OA_L = 1280;
    constexpr int OB_H = 2560;
    constexpr int OB_L = 7680;
    constexpr int STG  = 8960;
    constexpr uint32_t STGB = STG * 4;

    uint32_t* Ahs = smem_dyn;

    const int m0 = blockIdx.x * 64;
    const int tid = threadIdx.x, lane = tid & 31, wid = tid >> 5;
    const int wn = wid;

    const uint32_t sbase = (uint32_t)__cvta_generic_to_shared(smem_dyn);

    const int arowoff = ((lane >> 3) & 1) * 8 + (lane & 7);
    const int akoff   = (lane >> 4) * 4;
    uint32_t a_addr[4];
    #pragma unroll
    for (int mt = 0; mt < 4; mt++)
        a_addr[mt] = sbase + ((mt * 16 + arowoff) * SP + akoff) * 4;
    const uint32_t dAl = OA_L * 4;
    const int lb = lane & 15;
    uint32_t b_addr[4], bl_addr;
    #pragma unroll
    for (int j = 0; j < 4; j++)
        b_addr[j] = sbase + (OB_H + (wn * 8 + j * 64 + (lb & 7)) * SP
                             + ((lb >> 3) & 1) * 4) * 4;
    bl_addr = sbase + (OB_L + (wn * 8 + (lb & 7)) * SP + ((lb >> 3) & 1) * 4) * 4;

    const int ar = tid >> 3, afq = (tid & 7) * 4;
    const int aso = ar * SP + (afq >> 1);
    const int br = tid >> 2, bc = (tid & 3) * 4;

    float4 va[2];
    auto ldgA = [&](int k0) {
        #pragma unroll
        for (int e = 0; e < 2; e++)
            va[e] = *(const float4*)(xg + (long)(m0 + ar + e*32) * DD + k0 + afq);
    };
    auto cpB = [&](int k0, int s) {
        uint32_t d0 = sbase + (s * STG + OB_H + br * SP + bc) * 4;
        #pragma unroll
        for (int e = 0; e < 4; e++)
            cp16(d0 + e * 64 * SP * 4, &Wh[(br + e*64) * 512 + (k0 >> 1) + bc]);
        cp16(sbase + (s * STG + OB_L + br * SP + bc) * 4,
             &Wl[br * 512 + (k0 >> 1) + bc]);
        cp_commit();
    };
    auto stA = [&](int s) {
        #pragma unroll
        for (int e = 0; e < 2; e++) {
            float4 v = va[e];
            __nv_bfloat162 h0, l0, h1, l1;
            cvt_hilo(v.x, v.y, h0, l0);  cvt_hilo(v.z, v.w, h1, l1);
            int o = s * STG + aso + e * 32 * SP;
            Ahs[o]        = b2u(h0);  Ahs[o + 1]        = b2u(h1);
            Ahs[OA_L + o] = b2u(l0);  Ahs[OA_L + o + 1] = b2u(l1);
        }
    };

    float acc[4][4][4] = {};

    ldgA(0);
    cpB(0, 0);
    stA(0);
    cp_wait0();
    __syncthreads();

    int s = 0;
    for (int k0 = 0; k0 < DD; k0 += 32, s ^= 1) {
        const bool more = (k0 + 32) < DD;
        if (more) {
            ldgA(k0 + 32);
            cpB(k0 + 32, s ^ 1);
        }

        const uint32_t so = s * STGB;
        #pragma unroll
        for (int kp = 0; kp < 2; kp++) {
            const uint32_t kb = so + kp * 32;
            uint32_t bh[4][2], bl2[2];
            #pragma unroll
            for (int j = 0; j < 4; j++) ldmx2(bh[j], b_addr[j] + kb);
            ldmx2(bl2, bl_addr + kb);
            #pragma unroll
            for (int mt = 0; mt < 4; mt++) {
                uint32_t ah4[4], al4[4];
                ldmx4(ah4, a_addr[mt] + kb);
                #pragma unroll
                for (int j = 0; j < 4; j++)
                    mma_bf16(acc[mt][j], ah4, bh[j]);
                ldmx4(al4, a_addr[mt] + dAl + kb);
                mma_bf16(acc[mt][2], ah4, bl2);    // hi*lo (F)
                mma_bf16(acc[mt][2], al4, bh[2]);  // lo*hi (F)
            }
        }

        if (more) stA(s ^ 1);
        cp_wait0();
        __syncthreads();
    }

    const int r4 = lane >> 2, c4 = lane & 3;
    #pragma unroll
    for (int mt = 0; mt < 4; mt++)
        #pragma unroll
        for (int j = 0; j < 4; j++) {
            int row = m0 + mt * 16 + r4;
            int col = wn * 8 + j * 64 + 2 * c4;
            *(float2*)(Cg + (long)row * 256 + col) =
                make_float2(acc[mt][j][0], acc[mt][j][1]);
            *(float2*)(Cg + (long)(row + 8) * 256 + col) =
                make_float2(acc[mt][j][2], acc[mt][j][3]);
        }
}

// ===========================================================================
// fcout: fused fc + out. Phase 1 identical to R13. Phase 2: A fragments
// (fc bf16 planes) are loop-invariant — hoisted into registers ONCE before
// the 16-n-tile loop (the Ah/Al smem regions are never rewritten), removing
// 16 redundant ldmatrix.x4 per iteration. B path unchanged.
// ===========================================================================
__global__ void __launch_bounds__(256, 2)
fcout(const float* __restrict__ qkfp, const float* __restrict__ T,
      const uint32_t* __restrict__ W2h, const uint32_t* __restrict__ W2l,
      float* __restrict__ out)
{
    constexpr int SP = 36;
    constexpr int O_TS = 4352;
    constexpr int O_AH = 8704;
    constexpr int O_AL = 11008;
    constexpr int O_B  = 13312;
    constexpr int BSTG = 4608;
    constexpr int O_BL = 2304;

    float*    Qs  = (float*)smem_dyn;
    float*    Ts  = (float*)smem_dyn + O_TS;
    uint32_t* Ahp = smem_dyn + O_AH;
    uint32_t* Alp = smem_dyn + O_AL;

    const int r0 = blockIdx.x * 64;
    const int b  = r0 / NSEQ;
    const int tid = threadIdx.x, lane = tid & 31, wid = tid >> 5;
    const uint32_t sbase = (uint32_t)__cvta_generic_to_shared(smem_dyn);

    // ---------------- Phase 1: fc (identical to R13) ----------------
    #pragma unroll
    for (int e = 0; e < 4; e++) {
        int idx = tid + e * 256;
        int row = idx >> 4, fq = idx & 15;
        float4 q = *(const float4*)(qkfp + (long)(r0 + row) * 256 + fq * 4);
        *(float4*)&Qs[row * 68 + fq * 4] = q;
        float4 t = *(const float4*)(T + (long)b * 4096 + row * 64 + fq * 4);
        *(float4*)&Ts[row * 68 + fq * 4] = t;
    }
    __syncthreads();

    {
        const int row  = tid >> 2;
        const int col0 = (tid & 3) * 16;
        float acc[16];
        #pragma unroll
        for (int j = 0; j < 16; j += 4) {
            float4 f = *(const float4*)(qkfp + (long)(r0 + row) * 256 + 128 + col0 + j);
            acc[j] = f.x; acc[j+1] = f.y; acc[j+2] = f.z; acc[j+3] = f.w;
        }
        #pragma unroll 8
        for (int k = 0; k < 64; k++) {
            float q = Qs[row * 68 + k];
            #pragma unroll
            for (int j = 0; j < 16; j += 4) {
                float4 t = *(const float4*)&Ts[k * 68 + col0 + j];
                acc[j]   += q * t.x;  acc[j+1] += q * t.y;
                acc[j+2] += q * t.z;  acc[j+3] += q * t.w;
            }
        }
        const int ob = row * SP + (col0 >> 1);
        #pragma unroll
        for (int jj = 0; jj < 8; jj++) {
            __nv_bfloat162 h, l;
            cvt_hilo(acc[2*jj], acc[2*jj + 1], h, l);
            Ahp[ob + jj] = b2u(h);
            Alp[ob + jj] = b2u(l);
        }
    }
    __syncthreads();   // fc planes visible block-wide before fragment hoist

    // ---------------- Phase 2 ----------------
    const int wm0 = (wid & 1) * 32, wn0 = (wid >> 1) * 16;
    const int arowoff = ((lane >> 3) & 1) * 8 + (lane & 7);
    const int akoff   = (lane >> 4) * 4;
    uint32_t a_addr[2];
    #pragma unroll
    for (int mt = 0; mt < 2; mt++)
        a_addr[mt] = sbase + (O_AH + (wm0 + mt * 16 + arowoff) * SP + akoff) * 4;
    const uint32_t dAl = (O_AL - O_AH) * 4;
    const int lb = lane & 15;
    uint32_t b_addr[2];
    #pragma unroll
    for (int nt = 0; nt < 2; nt++)
        b_addr[nt] = sbase + (O_B + (wn0 + nt * 8 + (lb & 7)) * SP
                              + ((lb >> 3) & 1) * 4) * 4;
    const uint32_t dBl = O_BL * 4;

    // hoist ALL A fragments (loop-invariant; Ah/Al never rewritten)
    uint32_t ahF[4][2][4], alF[4][2][4];
    #pragma unroll
    for (int kp = 0; kp < 4; kp++) {
        #pragma unroll
        for (int mt = 0; mt < 2; mt++) {
            ldmx4(ahF[kp][mt], a_addr[mt] + kp * 32);
            ldmx4(alF[kp][mt], a_addr[mt] + dAl + kp * 32);
        }
    }

    const int wr = tid >> 3, wc = (tid & 7) * 4;
    auto cpW = [&](int nt, int s) {
        uint32_t d0 = sbase + (O_B + s * BSTG + wr * SP + wc) * 4;
        cp16(d0,            &W2h[(long)(nt * 64 + wr) * 32 + wc]);
        cp16(d0 + dBl,      &W2l[(long)(nt * 64 + wr) * 32 + wc]);
        uint32_t d1 = sbase + (O_B + s * BSTG + (wr + 32) * SP + wc) * 4;
        cp16(d1,            &W2h[(long)(nt * 64 + wr + 32) * 32 + wc]);
        cp16(d1 + dBl,      &W2l[(long)(nt * 64 + wr + 32) * 32 + wc]);
        cp_commit();
    };

    cpW(0, 0);

    const int r4 = lane >> 2, c4 = lane & 3;
    int s = 0;
    for (int nt = 0; nt < 16; nt++, s ^= 1) {
        if (nt < 15) {
            cpW(nt + 1, s ^ 1);
            cp_wait1();
        } else {
            cp_wait0();
        }
        __syncthreads();

        const uint32_t sB = s * BSTG * 4;
        float acc[2][2][4] = {};
        #pragma unroll
        for (int kp = 0; kp < 4; kp++) {
            const uint32_t kb = kp * 32;
            uint32_t bh[2][2], bl[2][2];
            #pragma unroll
            for (int ns = 0; ns < 2; ns++) ldmx2(bh[ns], b_addr[ns] + sB + kb);
            #pragma unroll
            for (int ns = 0; ns < 2; ns++) ldmx2(bl[ns], b_addr[ns] + sB + dBl + kb);
            #pragma unroll
            for (int mt = 0; mt < 2; mt++)
                #pragma unroll
                for (int ns = 0; ns < 2; ns++) {
                    mma_bf16(acc[mt][ns], ahF[kp][mt], bh[ns]);
                    mma_bf16(acc[mt][ns], ahF[kp][mt], bl[ns]);
                    mma_bf16(acc[mt][ns], alF[kp][mt], bh[ns]);
                }
        }

        #pragma unroll
        for (int mt = 0; mt < 2; mt++)
            #pragma unroll
            for (int ns = 0; ns < 2; ns++) {
                int row = r0 + wm0 + mt * 16 + r4;
                int col = nt * 64 + wn0 + ns * 8 + 2 * c4;
                *(float2*)(out + (long)row * 1024 + col) =
                    make_float2(acc[mt][ns][0], acc[mt][ns][1]);
                *(float2*)(out + (long)(row + 8) * 1024 + col) =
                    make_float2(acc[mt][ns][2], acc[mt][ns][3]);
            }
        __syncthreads();
    }
}

// ===========================================================================
// Tensor GEMM (tf32), ATB form: C[64,N] = A[L,64]^T * B[L,N] over rows L.
// ===========================================================================
__global__ void __launch_bounds__(256)
tgemm_atb(const float* __restrict__ Ag, int lda, long sAb,
          const float* __restrict__ Bg, int ldb, long sBb,
          float* __restrict__ Cg, long sCb, long sCsplit, int ldc,
          int Lchunk)
{
    constexpr int BK = 16, LDT = 64 + 4;
    __shared__ float As[BK][LDT];
    __shared__ float Bs[BK][LDT];

    const int b = blockIdx.z, sp = blockIdx.y;
    const long l0b = (long)sp * Lchunk;
    Ag += (long)b * sAb;  Bg += (long)b * sBb;
    Cg += (long)b * sCb + (long)sp * sCsplit;
    const int n0 = blockIdx.x * 64;
    const int tid = threadIdx.x, lane = tid & 31, wid = tid >> 5;
    const int wm0 = (wid & 1) * 32, wn0 = (wid >> 1) * 16;
    const int r4 = lane >> 2, c4 = lane & 3;
    const int lrow = tid >> 4, lc4 = (tid & 15) * 4;

    float acc[2][2][4] = {};
    float4 va, vb;

    auto ldg = [&](int l0) {
        va = *(const float4*)(Ag + (l0b + l0 + lrow) * lda + lc4);
        vb = *(const float4*)(Bg + (l0b + l0 + lrow) * ldb + n0 + lc4);
    };
    auto store = [&]() {
        As[lrow][lc4+0] = tf32_rna(va.x);  As[lrow][lc4+1] = tf32_rna(va.y);
        As[lrow][lc4+2] = tf32_rna(va.z);  As[lrow][lc4+3] = tf32_rna(va.w);
        Bs[lrow][lc4+0] = tf32_rna(vb.x);  Bs[lrow][lc4+1] = tf32_rna(vb.y);
        Bs[lrow][lc4+2] = tf32_rna(vb.z);  Bs[lrow][lc4+3] = tf32_rna(vb.w);
    };

    ldg(0);
    store();
    __syncthreads();

    for (int l0 = 0; l0 < Lchunk; l0 += BK) {
        const bool more = (l0 + BK) < Lchunk;
        if (more) ldg(l0 + BK);

        #pragma unroll
        for (int kk = 0; kk < BK; kk += 8) {
            uint32_t af[2][4], bf[2][2];
            #pragma unroll
            for (int mt = 0; mt < 2; mt++) {
                int row = wm0 + mt*16 + r4;
                af[mt][0] = f2u(As[kk + c4    ][row    ]);
                af[mt][1] = f2u(As[kk + c4    ][row + 8]);
                af[mt][2] = f2u(As[kk + c4 + 4][row    ]);
                af[mt][3] = f2u(As[kk + c4 + 4][row + 8]);
            }
            #pragma unroll
            for (int nt = 0; nt < 2; nt++) {
                int col = wn0 + nt*8 + r4;
                bf[nt][0] = f2u(Bs[kk + c4    ][col]);
                bf[nt][1] = f2u(Bs[kk + c4 + 4][col]);
            }
            #pragma unroll
            for (int mt = 0; mt < 2; mt++)
                #pragma unroll
                for (int nt = 0; nt < 2; nt++)
                    mma_tf32(acc[mt][nt], af[mt][0], af[mt][1], af[mt][2], af[mt][3],
                             bf[nt][0], bf[nt][1]);
        }
        __syncthreads();
        if (more) {
            store();
            __syncthreads();
        }
    }
    #pragma unroll
    for (int mt = 0; mt < 2; mt++)
        #pragma unroll
        for (int nt = 0; nt < 2; nt++) {
            int row = wm0 + mt*16 + r4;
            int col = n0 + wn0 + nt*8 + 2*c4;
            *(float2*)(Cg + (long)row * ldc + col) =
                make_float2(acc[mt][nt][0], acc[mt][nt][1]);
            *(float2*)(Cg + (long)(row + 8) * ldc + col) =
                make_float2(acc[mt][nt][2], acc[mt][nt][3]);
        }
}

// ===========================================================================
// SIMT fp32 NN GEMM (U2 only): C[M,N] = A[M,K]*B[K,N], split-K via z
// ===========================================================================
template<int BM,int BN,int BK,int TM,int TN>
__global__ void __launch_bounds__((BM/TM)*(BN/TN))
gemm_nn(const float* __restrict__ A, long sA, int lda,
        const float* __restrict__ B, long sB, int ldb,
        float* __restrict__ C, long sC, int ldc,
        int K)
{
    constexpr int THREADS = (BM/TM)*(BN/TN);
    __shared__ float As[BK][BM];
    __shared__ float Bs[BK][BN];

    const int bz = blockIdx.z;
    A += bz * sA;  B += bz * sB;  C += bz * sC;

    const int m0 = blockIdx.y * BM;
    const int n0 = blockIdx.x * BN;
    const int tid = threadIdx.x;
    const int tx = tid % (BN/TN);
    const int ty = tid / (BN/TN);

    float acc[TM][TN];
    #pragma unroll
    for (int i = 0; i < TM; i++)
        #pragma unroll
        for (int j = 0; j < TN; j++) acc[i][j] = 0.f;

    for (int k0 = 0; k0 < K; k0 += BK) {
        #pragma unroll
        for (int e = 0; e < (BM*BK/4)/THREADS; e++) {
            int idx = tid + e*THREADS;
            int row = idx / (BK/4), cv = idx % (BK/4);
            float4 v = *(const float4*)(A + (long)(m0+row)*lda + k0 + cv*4);
            As[cv*4+0][row] = v.x;  As[cv*4+1][row] = v.y;
            As[cv*4+2][row] = v.z;  As[cv*4+3][row] = v.w;
        }
        #pragma unroll
        for (int e = 0; e < (BK*BN/4)/THREADS; e++) {
            int idx = tid + e*THREADS;
            int row = idx / (BN/4), cv = idx % (BN/4);
            *(float4*)&Bs[row][cv*4] =
                *(const float4*)(B + (long)(k0+row)*ldb + n0 + cv*4);
        }
        __syncthreads();
        #pragma unroll
        for (int k = 0; k < BK; k++) {
            float a[TM], b[TN];
            #pragma unroll
            for (int i = 0; i < TM; i += 4) *(float4*)(a+i) = *(const float4*)&As[k][ty*TM+i];
            #pragma unroll
            for (int j = 0; j < TN; j += 4) *(float4*)(b+j) = *(const float4*)&Bs[k][tx*TN+j];
            #pragma unroll
            for (int i = 0; i < TM; i++)
                #pragma unroll
                for (int j = 0; j < TN; j++) acc[i][j] += a[i]*b[j];
        }
        __syncthreads();
    }
    #pragma unroll
    for (int i = 0; i < TM; i++) {
        int row = m0 + ty*TM + i;
        #pragma unroll
        for (int j = 0; j < TN; j += 4) {
            float4 v;
            v.x = acc[i][j];   v.y = acc[i][j+1];
            v.z = acc[i][j+2]; v.w = acc[i][j+3];
            *(float4*)(C + (long)row*ldc + n0 + tx*TN + j) = v;
        }
    }
}

// Sum S split partials
template<int S>
__global__ void reduceN(const float* __restrict__ p, float* __restrict__ o, int n)
{
    int i = blockIdx.x * 256 + threadIdx.x;
    if (i < n) {
        float s = 0.f;
        #pragma unroll
        for (int j = 0; j < S; j++) s += p[i + (long)j * n];
        o[i] = s;
    }
}

// ============================================================================
extern "C" void kernel_launch(void* const* d_in, const int* in_sizes, int n_in,
                              void* d_out, int out_size)
{
    const float* x  = (const float*)d_in[0];   // [8,2048,1024]
    const float* Wq = (const float*)d_in[1];   // [64,1024]
    const float* Wk = (const float*)d_in[2];   // [64,1024]
    const float* Wv = (const float*)d_in[3];   // [1024,1024]
    const float* W1 = (const float*)d_in[4];   // [64,1024]
    const float* W2 = (const float*)d_in[5];   // [1024,64]
    float* out = (float*)d_out;                // [8,2048,1024]

    float *qkfp, *u2p, *tpart, *gt;
    uint32_t *wh, *wl, *w2h, *w2l;
    cudaGetSymbolAddress((void**)&qkfp,  g_QKFP);
    cudaGetSymbolAddress((void**)&u2p,   g_U2part);
    cudaGetSymbolAddress((void**)&tpart, g_Tpart);
    cudaGetSymbolAddress((void**)&gt,    g_T);
    cudaGetSymbolAddress((void**)&wh,    g_Wh);
    cudaGetSymbolAddress((void**)&wl,    g_Wl);
    cudaGetSymbolAddress((void**)&w2h,   g_W2h);
    cudaGetSymbolAddress((void**)&w2l,   g_W2l);

    static_assert(2 * 8960 * 4 == 71680, "qkfp stage size");
    cudaFuncSetAttribute(qkfp_fused,
                         cudaFuncAttributeMaxDynamicSharedMemorySize, 71680);
    static_assert(22528 * 4 == 90112, "fcout smem size");
    cudaFuncSetAttribute(fcout,
                         cudaFuncAttributeMaxDynamicSharedMemorySize, 90112);

    // U2 = W1 @ Wv : [64,1024], 32-way split-K partials
    gemm_nn<64,64,16,4,4><<<dim3(16,1,32), 256>>>(
        W1, 32, DD,  Wv, (long)32*DD, DD,  u2p, (long)DKK*DD, DD,  32);

    // Build all bf16 weight planes
    prep_w<<<(256*512 + 1024*32 + 255)/256, 256>>>(
        Wq, Wk, W1, u2p, W2, wh, wl, w2h, w2l);

    // QKFP = x @ Wext^T : one pass over x, F columns split, 2 blocks/SM
    qkfp_fused<<<256, 256, 71680>>>(x, wh, wl, qkfp);

    // T_b partials = K_b^T P_b : 32-way L-split + reduce
    tgemm_atb<<<dim3(1, 32, 8), 256>>>(
        qkfp + 64,  256, (long)NSEQ*256,
        qkfp + 192, 256, (long)NSEQ*256,
        tpart, (long)DKK*DKK, (long)BB*DKK*DKK, DKK,
        NSEQ/32);
    reduceN<32><<<(BB*DKK*DKK + 255)/256, 256>>>(tpart, gt, BB*DKK*DKK);

    // fused fc + out (A fragments hoisted)
    fcout<<<256, 256, 90112>>>(qkfp, gt, w2h, w2l, out);
}